// round 7
// baseline (speedup 1.0000x reference)
#include <cuda_runtime.h>
#include <math.h>
#include <stdint.h>

#define BB 4
#define SS 1024
#define DD 512
#define HH 8
#define HD 64
#define NP 1025   // pemb rows (2*512+1)

// ---------------- scratch (device globals; allocation-free) ----------------
__device__ float g_q[BB*HH*SS*HD];              // [b,h,s,d], pre-scaled by 0.125
__device__ float g_k[BB*HH*SS*HD];
__device__ float g_v[BB*HH*SS*HD];
__device__ float g_qp[(size_t)BB*HH*SS*NP];     // [b,h,s, 1025]
__device__ float g_ctx[BB*SS*HH*HD];            // [b,s, h*64+d]

// ---------------- helpers ----------------
__device__ __forceinline__ uint32_t f2tf32(float f) {
    uint32_t u;
    asm("cvt.rna.tf32.f32 %0, %1;" : "=r"(u) : "f"(f));
    return u;
}

__device__ __forceinline__ void mma_tf32(float* c, const uint32_t* a, const uint32_t* b) {
    asm volatile(
        "mma.sync.aligned.m16n8k8.row.col.f32.tf32.tf32.f32 "
        "{%0,%1,%2,%3},{%4,%5,%6,%7},{%8,%9},{%0,%1,%2,%3};\n"
        : "+f"(c[0]), "+f"(c[1]), "+f"(c[2]), "+f"(c[3])
        : "r"(a[0]), "r"(a[1]), "r"(a[2]), "r"(a[3]),
          "r"(b[0]), "r"(b[1]));
}

// ============================================================================
// Generic tf32 GEMM: C[M,N] = A[M,K] @ B[K,N], BM=128, BN=64, BK=16,
// 256 threads = 8 warps in 4(m) x 2(n); each warp 32x32 = 2 m-tiles x 4 n-tiles.
// MODE 0: QKV projection (A=x, B=Wq|Wkv, scatter epilogue, q *= 0.125)
// MODE 1: QP (A=g_q, B=pemb^T, K=64, N=1025 with guard)
// MODE 2: out proj (A=g_ctx, B=Wout, bias add)
// ============================================================================
template<int MODE>
__global__ __launch_bounds__(256) void gemm_tf32(const float* __restrict__ A,
                                                 const float* __restrict__ B,
                                                 const float* __restrict__ B2,
                                                 const float* __restrict__ bias,
                                                 float* __restrict__ Cout) {
    constexpr int K = (MODE == 1) ? 64 : 512;
    __shared__ uint32_t As[128][20];   // [m][k], stride 20 -> conflict-free a-frag loads
    __shared__ uint32_t Bs[16][72];    // [k][n], stride 72 -> conflict-free b-frag loads

    const int m0 = blockIdx.y * 128;
    const int n0 = blockIdx.x * 64;
    const int tid = threadIdx.x;
    const int lane = tid & 31;
    const int w = tid >> 5;
    const int wm = w & 3;        // 0..3 -> 32-row group
    const int wn = w >> 2;       // 0..1 -> 32-col group
    const int group = lane >> 2; // 0..7
    const int tid4 = lane & 3;   // 0..3

    const float* Aptr = (MODE == 0) ? A : (MODE == 1 ? g_q : g_ctx);

    float c[2][4][4] = {};

    for (int k0 = 0; k0 < K; k0 += 16) {
        // ---- load A tile (128 x 16) ----
        {
            int row = tid >> 1;
            #pragma unroll
            for (int j = 0; j < 2; j++) {
                int cg = (tid & 1) * 8 + j * 4;
                float4 v = *(const float4*)&Aptr[(size_t)(m0 + row) * K + k0 + cg];
                As[row][cg + 0] = f2tf32(v.x);
                As[row][cg + 1] = f2tf32(v.y);
                As[row][cg + 2] = f2tf32(v.z);
                As[row][cg + 3] = f2tf32(v.w);
            }
        }
        // ---- load B tile (16 x 64) ----
        if (MODE == 0) {
            int kk = tid >> 4, cg = (tid & 15) * 4;
            int n = n0 + cg;
            float4 v;
            if (n < 512) v = *(const float4*)&B [(size_t)(k0 + kk) * 512  + n];
            else         v = *(const float4*)&B2[(size_t)(k0 + kk) * 1024 + (n - 512)];
            Bs[kk][cg + 0] = f2tf32(v.x);
            Bs[kk][cg + 1] = f2tf32(v.y);
            Bs[kk][cg + 2] = f2tf32(v.z);
            Bs[kk][cg + 3] = f2tf32(v.w);
        } else if (MODE == 2) {
            int kk = tid >> 4, cg = (tid & 15) * 4;
            float4 v = *(const float4*)&B[(size_t)(k0 + kk) * 512 + n0 + cg];
            Bs[kk][cg + 0] = f2tf32(v.x);
            Bs[kk][cg + 1] = f2tf32(v.y);
            Bs[kk][cg + 2] = f2tf32(v.z);
            Bs[kk][cg + 3] = f2tf32(v.w);
        } else {
            // B(k,n) = pemb[n][k] -> transpose on load
            int nl = tid >> 2, kg = (tid & 3) * 4;
            int n = n0 + nl;
            float4 v = make_float4(0.f, 0.f, 0.f, 0.f);
            if (n < NP) v = *(const float4*)&B[(size_t)n * HD + k0 + kg];
            Bs[kg + 0][nl] = f2tf32(v.x);
            Bs[kg + 1][nl] = f2tf32(v.y);
            Bs[kg + 2][nl] = f2tf32(v.z);
            Bs[kg + 3][nl] = f2tf32(v.w);
        }
        __syncthreads();

        #pragma unroll
        for (int ks = 0; ks < 16; ks += 8) {
            uint32_t a[2][4];
            #pragma unroll
            for (int mt = 0; mt < 2; mt++) {
                int r = wm * 32 + mt * 16;
                a[mt][0] = As[r + group    ][ks + tid4    ];
                a[mt][1] = As[r + group + 8][ks + tid4    ];
                a[mt][2] = As[r + group    ][ks + tid4 + 4];
                a[mt][3] = As[r + group + 8][ks + tid4 + 4];
            }
            #pragma unroll
            for (int nt = 0; nt < 4; nt++) {
                int cidx = wn * 32 + nt * 8 + group;
                uint32_t b[2];
                b[0] = Bs[ks + tid4    ][cidx];
                b[1] = Bs[ks + tid4 + 4][cidx];
                #pragma unroll
                for (int mt = 0; mt < 2; mt++)
                    mma_tf32(c[mt][nt], a[mt], b);
            }
        }
        __syncthreads();
    }

    // ---- epilogue ----
    #pragma unroll
    for (int mt = 0; mt < 2; mt++) {
        #pragma unroll
        for (int nt = 0; nt < 4; nt++) {
            #pragma unroll
            for (int e = 0; e < 4; e++) {
                int row = m0 + wm * 32 + mt * 16 + group + ((e >> 1) * 8);
                int col = n0 + wn * 32 + nt * 8 + 2 * tid4 + (e & 1);
                float val = c[mt][nt][e];
                if (MODE == 0) {
                    int b = row >> 10, s = row & 1023;
                    float* dst; int hcol;
                    if (col < 512)       { dst = g_q; hcol = col;        val *= 0.125f; }
                    else if (col < 1024) { dst = g_k; hcol = col - 512;  }
                    else                 { dst = g_v; hcol = col - 1024; }
                    int h = hcol >> 6, d = hcol & 63;
                    dst[(((size_t)(b * HH + h) << 10) + s) * HD + d] = val;
                } else if (MODE == 1) {
                    if (col < NP) g_qp[(size_t)row * NP + col] = val;
                } else {
                    Cout[(size_t)row * DD + col] = val + bias[col];
                }
            }
        }
    }
}

// ============================================================================
// Flash attention on tf32 mma: q-tile 64, k-tile 32, 256 threads = 8 warps
// in 4(row) x 2(col). Positional bias gathered from g_qp per C element.
// ============================================================================
__global__ __launch_bounds__(256) void attn_mma() {
    const int bh = blockIdx.y;
    const int q0 = blockIdx.x * 64;
    const int tid = threadIdx.x;
    const int lane = tid & 31;
    const int w = tid >> 5;
    const int wm = w & 3;        // 16-row group within q tile
    const int wn = w >> 2;       // 0/1: 16-col group for S, 32-col group for O
    const int group = lane >> 2;
    const int tid4 = lane & 3;

    __shared__ uint32_t sQ[64][68];
    __shared__ uint32_t sK[32][68];
    __shared__ uint32_t sV[32][72];
    __shared__ uint32_t sP[64][36];
    __shared__ float redM[2][64];
    __shared__ float redS[2][64];

    // load Q tile (tf32)
    #pragma unroll
    for (int j = 0; j < 4; j++) {
        int idx = tid + j * 256;
        int row = idx >> 4, cg = (idx & 15) * 4;
        float4 v = *(const float4*)&g_q[((size_t)bh * SS + q0 + row) * HD + cg];
        sQ[row][cg + 0] = f2tf32(v.x);
        sQ[row][cg + 1] = f2tf32(v.y);
        sQ[row][cg + 2] = f2tf32(v.z);
        sQ[row][cg + 3] = f2tf32(v.w);
    }

    float cO[4][4] = {};
    float rmax0 = -1e30f, rmax1 = -1e30f;
    float rsum0 = 0.f, rsum1 = 0.f;
    const int row0 = wm * 16 + group;       // local row of c0/c1
    const int row1 = row0 + 8;              // local row of c2/c3
    const size_t qpb0 = ((size_t)bh * SS + q0 + row0) * NP + 512;
    const size_t qpb1 = ((size_t)bh * SS + q0 + row1) * NP + 512;

    for (int kt = 0; kt < SS / 32; kt++) {
        const int t0 = kt * 32;
        // load K,V tiles (32x64)
        #pragma unroll
        for (int j = 0; j < 2; j++) {
            int idx = tid + j * 256;
            int row = idx >> 4, cg = (idx & 15) * 4;
            size_t base = ((size_t)bh * SS + t0 + row) * HD + cg;
            float4 kv = *(const float4*)&g_k[base];
            sK[row][cg + 0] = f2tf32(kv.x);
            sK[row][cg + 1] = f2tf32(kv.y);
            sK[row][cg + 2] = f2tf32(kv.z);
            sK[row][cg + 3] = f2tf32(kv.w);
            float4 vv = *(const float4*)&g_v[base];
            sV[row][cg + 0] = f2tf32(vv.x);
            sV[row][cg + 1] = f2tf32(vv.y);
            sV[row][cg + 2] = f2tf32(vv.z);
            sV[row][cg + 3] = f2tf32(vv.w);
        }
        __syncthreads();

        // ---- S = Q @ K^T (16 rows x 16 cols per warp) ----
        float cS[2][4] = {};
        #pragma unroll
        for (int ks = 0; ks < 8; ks++) {
            uint32_t a[4];
            a[0] = sQ[row0][ks * 8 + tid4    ];
            a[1] = sQ[row1][ks * 8 + tid4    ];
            a[2] = sQ[row0][ks * 8 + tid4 + 4];
            a[3] = sQ[row1][ks * 8 + tid4 + 4];
            #pragma unroll
            for (int nt = 0; nt < 2; nt++) {
                int kc = wn * 16 + nt * 8 + group;
                uint32_t b[2];
                b[0] = sK[kc][ks * 8 + tid4    ];
                b[1] = sK[kc][ks * 8 + tid4 + 4];
                mma_tf32(cS[nt], a, b);
            }
        }

        // ---- positional bias + per-warp row max ----
        float mloc0 = -1e30f, mloc1 = -1e30f;
        const int s0 = q0 + row0, s1 = q0 + row1;
        #pragma unroll
        for (int nt = 0; nt < 2; nt++) {
            #pragma unroll
            for (int e = 0; e < 4; e++) {
                int t = t0 + wn * 16 + nt * 8 + 2 * tid4 + (e & 1);
                int s_g = (e < 2) ? s0 : s1;
                int dlt = s_g - t;
                dlt = min(512, max(-512, dlt));
                float v = cS[nt][e] + g_qp[((e < 2) ? qpb0 : qpb1) + dlt];
                cS[nt][e] = v;
                if (e < 2) mloc0 = fmaxf(mloc0, v);
                else       mloc1 = fmaxf(mloc1, v);
            }
        }
        mloc0 = fmaxf(mloc0, __shfl_xor_sync(0xffffffffu, mloc0, 1));
        mloc0 = fmaxf(mloc0, __shfl_xor_sync(0xffffffffu, mloc0, 2));
        mloc1 = fmaxf(mloc1, __shfl_xor_sync(0xffffffffu, mloc1, 1));
        mloc1 = fmaxf(mloc1, __shfl_xor_sync(0xffffffffu, mloc1, 2));
        if (tid4 == 0) { redM[wn][row0] = mloc0; redM[wn][row1] = mloc1; }
        __syncthreads();

        float mnew0 = fmaxf(rmax0, fmaxf(redM[0][row0], redM[1][row0]));
        float mnew1 = fmaxf(rmax1, fmaxf(redM[0][row1], redM[1][row1]));
        float corr0 = __expf(rmax0 - mnew0);
        float corr1 = __expf(rmax1 - mnew1);
        rmax0 = mnew0; rmax1 = mnew1;

        float ls0 = 0.f, ls1 = 0.f;
        #pragma unroll
        for (int nt = 0; nt < 2; nt++) {
            #pragma unroll
            for (int e = 0; e < 4; e++) {
                float p = __expf(cS[nt][e] - ((e < 2) ? mnew0 : mnew1));
                if (e < 2) ls0 += p; else ls1 += p;
                int r = (e < 2) ? row0 : row1;
                sP[r][wn * 16 + nt * 8 + 2 * tid4 + (e & 1)] = f2tf32(p);
            }
        }
        ls0 += __shfl_xor_sync(0xffffffffu, ls0, 1);
        ls0 += __shfl_xor_sync(0xffffffffu, ls0, 2);
        ls1 += __shfl_xor_sync(0xffffffffu, ls1, 1);
        ls1 += __shfl_xor_sync(0xffffffffu, ls1, 2);
        if (tid4 == 0) { redS[wn][row0] = ls0; redS[wn][row1] = ls1; }
        __syncthreads();

        rsum0 = rsum0 * corr0 + redS[0][row0] + redS[1][row0];
        rsum1 = rsum1 * corr1 + redS[0][row1] + redS[1][row1];

        #pragma unroll
        for (int nt2 = 0; nt2 < 4; nt2++) {
            cO[nt2][0] *= corr0; cO[nt2][1] *= corr0;
            cO[nt2][2] *= corr1; cO[nt2][3] *= corr1;
        }

        // ---- O += P @ V (16 rows x 32 hd-cols per warp) ----
        #pragma unroll
        for (int ks = 0; ks < 4; ks++) {
            uint32_t a[4];
            a[0] = sP[row0][ks * 8 + tid4    ];
            a[1] = sP[row1][ks * 8 + tid4    ];
            a[2] = sP[row0][ks * 8 + tid4 + 4];
            a[3] = sP[row1][ks * 8 + tid4 + 4];
            #pragma unroll
            for (int nt2 = 0; nt2 < 4; nt2++) {
                int dc = wn * 32 + nt2 * 8 + group;
                uint32_t b[2];
                b[0] = sV[ks * 8 + tid4    ][dc];
                b[1] = sV[ks * 8 + tid4 + 4][dc];
                mma_tf32(cO[nt2], a, b);
            }
        }
        __syncthreads();
    }

    // ---- write ctx [b, s, h*64+d] ----
    const int b = bh >> 3, h = bh & 7;
    const float inv0 = 1.0f / rsum0, inv1 = 1.0f / rsum1;
    #pragma unroll
    for (int nt2 = 0; nt2 < 4; nt2++) {
        #pragma unroll
        for (int e = 0; e < 4; e++) {
            int d = wn * 32 + nt2 * 8 + 2 * tid4 + (e & 1);
            int s = q0 + ((e < 2) ? row0 : row1);
            float val = cO[nt2][e] * ((e < 2) ? inv0 : inv1);
            g_ctx[((size_t)(b * SS + s)) * (HH * HD) + h * HD + d] = val;
        }
    }
}

// ============================================================================
extern "C" void kernel_launch(void* const* d_in, const int* in_sizes, int n_in,
                              void* d_out, int out_size) {
    const float* x    = (const float*)d_in[0];
    // d_in[1] = attn_mask (unused by reference)
    const float* Wq   = (const float*)d_in[2];
    const float* Wkv  = (const float*)d_in[3];
    const float* Wout = (const float*)d_in[4];
    const float* bout = (const float*)d_in[5];
    const float* pemb = (const float*)d_in[6];
    float* out = (float*)d_out;

    // 1) QKV projection: M=4096, N=1536, K=512
    gemm_tf32<0><<<dim3(1536 / 64, 4096 / 128), 256>>>(x, Wq, Wkv, nullptr, nullptr);

    // 2) qp = q @ pemb^T: M=32768, N=1025, K=64
    gemm_tf32<1><<<dim3((NP + 63) / 64, (BB * HH * SS) / 128), 256>>>(nullptr, pemb, nullptr, nullptr, nullptr);

    // 3) attention: 16 q-tiles x 32 (b,h)
    attn_mma<<<dim3(SS / 64, BB * HH), 256>>>();

    // 4) out projection: M=4096, N=512, K=512
    gemm_tf32<2><<<dim3(DD / 64, 4096 / 128), 256>>>(nullptr, Wout, nullptr, bout, out);
}

// round 8
// speedup vs baseline: 1.1348x; 1.1348x over previous
#include <cuda_runtime.h>
#include <math.h>
#include <stdint.h>

#define BB 4
#define SS 1024
#define DD 512
#define HH 8
#define HD 64
#define NP 1025    // pemb rows (2*512+1)
#define QPS 1032   // padded qp row stride (16B-aligned rows)

// ---------------- scratch (device globals; allocation-free) ----------------
__device__ float g_q[BB*HH*SS*HD];              // [b,h,s,d], pre-scaled by 0.125
__device__ float g_k[BB*HH*SS*HD];
__device__ float g_v[BB*HH*SS*HD];
__device__ float g_qp[(size_t)BB*HH*SS*QPS];    // [b,h,s, 1032(1025 used)]
__device__ float g_ctx[BB*SS*HH*HD];            // [b,s, h*64+d]

// ---------------- helpers ----------------
__device__ __forceinline__ uint32_t f2tf32(float f) {
    uint32_t u;
    asm("cvt.rna.tf32.f32 %0, %1;" : "=r"(u) : "f"(f));
    return u;
}

__device__ __forceinline__ void mma_tf32(float* c, const uint32_t* a, const uint32_t* b) {
    asm volatile(
        "mma.sync.aligned.m16n8k8.row.col.f32.tf32.tf32.f32 "
        "{%0,%1,%2,%3},{%4,%5,%6,%7},{%8,%9},{%0,%1,%2,%3};\n"
        : "+f"(c[0]), "+f"(c[1]), "+f"(c[2]), "+f"(c[3])
        : "r"(a[0]), "r"(a[1]), "r"(a[2]), "r"(a[3]),
          "r"(b[0]), "r"(b[1]));
}

__device__ __forceinline__ void cpa16(void* smem_dst, const void* gsrc) {
    uint32_t a = (uint32_t)__cvta_generic_to_shared(smem_dst);
    asm volatile("cp.async.cg.shared.global [%0], [%1], 16;" :: "r"(a), "l"(gsrc));
}
__device__ __forceinline__ void cpa_commit() {
    asm volatile("cp.async.commit_group;");
}
template<int N>
__device__ __forceinline__ void cpa_wait() {
    asm volatile("cp.async.wait_group %0;" :: "n"(N));
}

// ============================================================================
// Generic tf32 GEMM, 2-stage cp.async pipeline.
// C[M,N] = A[M,K] @ B[K,N], BM=128, BN=64, BK=16, 256 threads = 8 warps in
// 4(m) x 2(n); each warp 32x32 = 2 m-tiles x 4 n-tiles of m16n8k8.
// MODE 0: QKV projection (A=x, B=Wq|Wkv, scatter epilogue, q *= 0.125)
// MODE 1: QP (A=g_q, B=pemb^T transposed on load, K=64, N=1025 guarded)
// MODE 2: out proj (A=g_ctx, B=Wout, bias add)
// ============================================================================
template<int MODE>
__global__ __launch_bounds__(256) void gemm_tf32(const float* __restrict__ A,
                                                 const float* __restrict__ B,
                                                 const float* __restrict__ B2,
                                                 const float* __restrict__ bias,
                                                 float* __restrict__ Cout) {
    constexpr int K = (MODE == 1) ? 64 : 512;
    constexpr int NIT = K / 16;
    constexpr int BSZ = (MODE == 1) ? 64 * 20 : 16 * 72;

    __shared__ float As[2][128][20];   // [m][k] raw fp32, stride 20 (conflict-free)
    __shared__ float Bs[2][BSZ];       // MODE!=1: [k][n] stride 72; MODE 1: [n][k] stride 20

    const int m0 = blockIdx.y * 128;
    const int n0 = blockIdx.x * 64;
    const int tid = threadIdx.x;
    const int lane = tid & 31;
    const int w = tid >> 5;
    const int wm = w & 3;
    const int wn = w >> 2;
    const int group = lane >> 2;
    const int tid4 = lane & 3;

    const float* Aptr = (MODE == 0) ? A : (MODE == 1 ? g_q : g_ctx);

    float c[2][4][4] = {};

    // ---- tile loaders (cp.async) ----
    auto loadA = [&](int buf, int k0) {
        int row = tid >> 1;
        int cg  = (tid & 1) * 8;
        const float* src = &Aptr[(size_t)(m0 + row) * K + k0 + cg];
        cpa16(&As[buf][row][cg],     src);
        cpa16(&As[buf][row][cg + 4], src + 4);
    };
    auto loadB = [&](int buf, int k0) {
        if (MODE == 1) {
            int nl = tid >> 2, kg = (tid & 3) * 4;
            int n = n0 + nl;
            if (n < NP) {
                cpa16(&Bs[buf][nl * 20 + kg], &B[(size_t)n * HD + k0 + kg]);
            } else {
                float* d = &Bs[buf][nl * 20 + kg];
                d[0] = d[1] = d[2] = d[3] = 0.f;
            }
        } else {
            int kk = tid >> 4, cg = (tid & 15) * 4;
            int n = n0 + cg;
            const float* src;
            if (MODE == 0) src = (n < 512) ? &B[(size_t)(k0 + kk) * 512 + n]
                                           : &B2[(size_t)(k0 + kk) * 1024 + (n - 512)];
            else           src = &B[(size_t)(k0 + kk) * 512 + n0 + cg];
            cpa16(&Bs[buf][kk * 72 + cg], src);
        }
    };

    loadA(0, 0); loadB(0, 0); cpa_commit();

    for (int i = 0; i < NIT; i++) {
        const int cur = i & 1;
        if (i + 1 < NIT) {
            loadA(cur ^ 1, (i + 1) * 16);
            loadB(cur ^ 1, (i + 1) * 16);
            cpa_commit();
            cpa_wait<1>();
        } else {
            cpa_wait<0>();
        }
        __syncthreads();

        #pragma unroll
        for (int ks = 0; ks < 16; ks += 8) {
            uint32_t a[2][4];
            #pragma unroll
            for (int mt = 0; mt < 2; mt++) {
                int r = wm * 32 + mt * 16;
                a[mt][0] = f2tf32(As[cur][r + group    ][ks + tid4    ]);
                a[mt][1] = f2tf32(As[cur][r + group + 8][ks + tid4    ]);
                a[mt][2] = f2tf32(As[cur][r + group    ][ks + tid4 + 4]);
                a[mt][3] = f2tf32(As[cur][r + group + 8][ks + tid4 + 4]);
            }
            #pragma unroll
            for (int nt = 0; nt < 4; nt++) {
                int cidx = wn * 32 + nt * 8 + group;
                uint32_t b[2];
                if (MODE == 1) {
                    b[0] = f2tf32(Bs[cur][cidx * 20 + ks + tid4    ]);
                    b[1] = f2tf32(Bs[cur][cidx * 20 + ks + tid4 + 4]);
                } else {
                    b[0] = f2tf32(Bs[cur][(ks + tid4    ) * 72 + cidx]);
                    b[1] = f2tf32(Bs[cur][(ks + tid4 + 4) * 72 + cidx]);
                }
                #pragma unroll
                for (int mt = 0; mt < 2; mt++)
                    mma_tf32(c[mt][nt], a[mt], b);
            }
        }
        __syncthreads();
    }

    // ---- epilogue ----
    #pragma unroll
    for (int mt = 0; mt < 2; mt++) {
        #pragma unroll
        for (int nt = 0; nt < 4; nt++) {
            #pragma unroll
            for (int e = 0; e < 4; e++) {
                int row = m0 + wm * 32 + mt * 16 + group + ((e >> 1) * 8);
                int col = n0 + wn * 32 + nt * 8 + 2 * tid4 + (e & 1);
                float val = c[mt][nt][e];
                if (MODE == 0) {
                    int b = row >> 10, s = row & 1023;
                    float* dst; int hcol;
                    if (col < 512)       { dst = g_q; hcol = col;        val *= 0.125f; }
                    else if (col < 1024) { dst = g_k; hcol = col - 512;  }
                    else                 { dst = g_v; hcol = col - 1024; }
                    int h = hcol >> 6, d = hcol & 63;
                    dst[(((size_t)(b * HH + h) << 10) + s) * HD + d] = val;
                } else if (MODE == 1) {
                    if (col < NP) g_qp[(size_t)row * QPS + col] = val;
                } else {
                    Cout[(size_t)row * DD + col] = val + bias[col];
                }
            }
        }
    }
}

// ============================================================================
// Flash attention on tf32 mma, cp.async double-buffered K/V, Q in registers.
// q-tile 64, k-tile 32, 256 threads = 8 warps in 4(row) x 2(col).
// ============================================================================
__global__ __launch_bounds__(256) void attn_mma() {
    const int bh = blockIdx.y;
    const int q0 = blockIdx.x * 64;
    const int tid = threadIdx.x;
    const int lane = tid & 31;
    const int w = tid >> 5;
    const int wm = w & 3;
    const int wn = w >> 2;
    const int group = lane >> 2;
    const int tid4 = lane & 3;

    __shared__ float sK[2][32][68];    // raw fp32
    __shared__ float sV[2][32][68];
    __shared__ float sPm[64][36];
    __shared__ float redM[2][64];
    __shared__ float redS[2][64];

    const int row0 = wm * 16 + group;
    const int row1 = row0 + 8;
    const size_t qbase = (size_t)bh * SS + q0;
    const size_t qpb0 = (qbase + row0) * QPS + 512;
    const size_t qpb1 = (qbase + row1) * QPS + 512;

    // ---- K/V tile prefetch (cp.async) ----
    auto loadKV = [&](int buf, int kt) {
        int t0 = kt * 32;
        int row = tid >> 3;
        int cg  = (tid & 7) * 8;
        size_t base = ((size_t)bh * SS + t0 + row) * HD + cg;
        cpa16(&sK[buf][row][cg],     &g_k[base]);
        cpa16(&sK[buf][row][cg + 4], &g_k[base + 4]);
        cpa16(&sV[buf][row][cg],     &g_v[base]);
        cpa16(&sV[buf][row][cg + 4], &g_v[base + 4]);
    };

    loadKV(0, 0); cpa_commit();

    // ---- preload Q fragments into registers (overlaps with tile-0 loads) ----
    uint32_t qa[8][4];
    #pragma unroll
    for (int ks = 0; ks < 8; ks++) {
        const float* p0 = &g_q[(qbase + row0) * HD + ks * 8 + tid4];
        const float* p1 = &g_q[(qbase + row1) * HD + ks * 8 + tid4];
        qa[ks][0] = f2tf32(p0[0]);
        qa[ks][1] = f2tf32(p1[0]);
        qa[ks][2] = f2tf32(p0[4]);
        qa[ks][3] = f2tf32(p1[4]);
    }

    float cO[4][4] = {};
    float rmax0 = -1e30f, rmax1 = -1e30f;
    float rsum0 = 0.f, rsum1 = 0.f;

    for (int kt = 0; kt < SS / 32; kt++) {
        const int cur = kt & 1;
        const int t0 = kt * 32;
        if (kt + 1 < SS / 32) {
            loadKV(cur ^ 1, kt + 1);
            cpa_commit();
            cpa_wait<1>();
        } else {
            cpa_wait<0>();
        }
        __syncthreads();

        // ---- S = Q @ K^T (16 rows x 16 cols per warp) ----
        float cS[2][4] = {};
        #pragma unroll
        for (int ks = 0; ks < 8; ks++) {
            #pragma unroll
            for (int nt = 0; nt < 2; nt++) {
                int kc = wn * 16 + nt * 8 + group;
                uint32_t b[2];
                b[0] = f2tf32(sK[cur][kc][ks * 8 + tid4    ]);
                b[1] = f2tf32(sK[cur][kc][ks * 8 + tid4 + 4]);
                mma_tf32(cS[nt], qa[ks], b);
            }
        }

        // ---- positional bias + per-warp row max ----
        float mloc0 = -1e30f, mloc1 = -1e30f;
        const int s0 = q0 + row0, s1 = q0 + row1;
        #pragma unroll
        for (int nt = 0; nt < 2; nt++) {
            #pragma unroll
            for (int e = 0; e < 4; e++) {
                int t = t0 + wn * 16 + nt * 8 + 2 * tid4 + (e & 1);
                int s_g = (e < 2) ? s0 : s1;
                int dlt = s_g - t;
                dlt = min(512, max(-512, dlt));
                float v = cS[nt][e] + g_qp[((e < 2) ? qpb0 : qpb1) + dlt];
                cS[nt][e] = v;
                if (e < 2) mloc0 = fmaxf(mloc0, v);
                else       mloc1 = fmaxf(mloc1, v);
            }
        }
        mloc0 = fmaxf(mloc0, __shfl_xor_sync(0xffffffffu, mloc0, 1));
        mloc0 = fmaxf(mloc0, __shfl_xor_sync(0xffffffffu, mloc0, 2));
        mloc1 = fmaxf(mloc1, __shfl_xor_sync(0xffffffffu, mloc1, 1));
        mloc1 = fmaxf(mloc1, __shfl_xor_sync(0xffffffffu, mloc1, 2));
        if (tid4 == 0) { redM[wn][row0] = mloc0; redM[wn][row1] = mloc1; }
        __syncthreads();

        float mnew0 = fmaxf(rmax0, fmaxf(redM[0][row0], redM[1][row0]));
        float mnew1 = fmaxf(rmax1, fmaxf(redM[0][row1], redM[1][row1]));
        float corr0 = __expf(rmax0 - mnew0);
        float corr1 = __expf(rmax1 - mnew1);
        rmax0 = mnew0; rmax1 = mnew1;

        float ls0 = 0.f, ls1 = 0.f;
        #pragma unroll
        for (int nt = 0; nt < 2; nt++) {
            #pragma unroll
            for (int e = 0; e < 4; e++) {
                float p = __expf(cS[nt][e] - ((e < 2) ? mnew0 : mnew1));
                if (e < 2) ls0 += p; else ls1 += p;
                int r = (e < 2) ? row0 : row1;
                sPm[r][wn * 16 + nt * 8 + 2 * tid4 + (e & 1)] = p;
            }
        }
        ls0 += __shfl_xor_sync(0xffffffffu, ls0, 1);
        ls0 += __shfl_xor_sync(0xffffffffu, ls0, 2);
        ls1 += __shfl_xor_sync(0xffffffffu, ls1, 1);
        ls1 += __shfl_xor_sync(0xffffffffu, ls1, 2);
        if (tid4 == 0) { redS[wn][row0] = ls0; redS[wn][row1] = ls1; }
        __syncthreads();

        rsum0 = rsum0 * corr0 + redS[0][row0] + redS[1][row0];
        rsum1 = rsum1 * corr1 + redS[0][row1] + redS[1][row1];

        #pragma unroll
        for (int nt2 = 0; nt2 < 4; nt2++) {
            cO[nt2][0] *= corr0; cO[nt2][1] *= corr0;
            cO[nt2][2] *= corr1; cO[nt2][3] *= corr1;
        }

        // ---- O += P @ V (16 rows x 32 hd-cols per warp) ----
        #pragma unroll
        for (int ks = 0; ks < 4; ks++) {
            uint32_t a[4];
            a[0] = f2tf32(sPm[row0][ks * 8 + tid4    ]);
            a[1] = f2tf32(sPm[row1][ks * 8 + tid4    ]);
            a[2] = f2tf32(sPm[row0][ks * 8 + tid4 + 4]);
            a[3] = f2tf32(sPm[row1][ks * 8 + tid4 + 4]);
            #pragma unroll
            for (int nt2 = 0; nt2 < 4; nt2++) {
                int dc = wn * 32 + nt2 * 8 + group;
                uint32_t b[2];
                b[0] = f2tf32(sV[cur][ks * 8 + tid4    ][dc]);
                b[1] = f2tf32(sV[cur][ks * 8 + tid4 + 4][dc]);
                mma_tf32(cO[nt2], a, b);
            }
        }
        __syncthreads();
    }

    // ---- write ctx [b, s, h*64+d] ----
    const int b = bh >> 3, h = bh & 7;
    const float inv0 = 1.0f / rsum0, inv1 = 1.0f / rsum1;
    #pragma unroll
    for (int nt2 = 0; nt2 < 4; nt2++) {
        #pragma unroll
        for (int e = 0; e < 4; e++) {
            int d = wn * 32 + nt2 * 8 + 2 * tid4 + (e & 1);
            int s = q0 + ((e < 2) ? row0 : row1);
            float val = cO[nt2][e] * ((e < 2) ? inv0 : inv1);
            g_ctx[((size_t)(b * SS + s)) * (HH * HD) + h * HD + d] = val;
        }
    }
}

// ============================================================================
extern "C" void kernel_launch(void* const* d_in, const int* in_sizes, int n_in,
                              void* d_out, int out_size) {
    const float* x    = (const float*)d_in[0];
    // d_in[1] = attn_mask (unused by reference)
    const float* Wq   = (const float*)d_in[2];
    const float* Wkv  = (const float*)d_in[3];
    const float* Wout = (const float*)d_in[4];
    const float* bout = (const float*)d_in[5];
    const float* pemb = (const float*)d_in[6];
    float* out = (float*)d_out;

    // 1) QKV projection: M=4096, N=1536, K=512
    gemm_tf32<0><<<dim3(1536 / 64, 4096 / 128), 256>>>(x, Wq, Wkv, nullptr, nullptr);

    // 2) qp = q @ pemb^T: M=32768, N=1025, K=64
    gemm_tf32<1><<<dim3((NP + 63) / 64, (BB * HH * SS) / 128), 256>>>(nullptr, pemb, nullptr, nullptr, nullptr);

    // 3) attention: 16 q-tiles x 32 (b,h)
    attn_mma<<<dim3(SS / 64, BB * HH), 256>>>();

    // 4) out projection: M=4096, N=512, K=512
    gemm_tf32<2><<<dim3(DD / 64, 4096 / 128), 256>>>(nullptr, Wout, nullptr, bout, out);
}

// round 9
// speedup vs baseline: 1.2380x; 1.0910x over previous
#include <cuda_runtime.h>
#include <math.h>
#include <stdint.h>

#define BB 4
#define SS 1024
#define DD 512
#define HH 8
#define HD 64
#define NP 1025    // pemb rows (2*512+1)
#define QPS 1032   // padded qp row stride (16B-aligned rows)

// ---------------- scratch (device globals; allocation-free) ----------------
__device__ float g_q[BB*HH*SS*HD];              // [b,h,s,d], pre-scaled by 0.125
__device__ float g_k[BB*HH*SS*HD];
__device__ float g_v[BB*HH*SS*HD];
__device__ float g_qp[(size_t)BB*HH*SS*QPS];    // [b,h,s, 1032(1025 used)]
__device__ float g_ctx[BB*SS*HH*HD];            // [b,s, h*64+d]

// ---------------- helpers ----------------
__device__ __forceinline__ uint32_t f2tf32(float f) {
    uint32_t u;
    asm("cvt.rna.tf32.f32 %0, %1;" : "=r"(u) : "f"(f));
    return u;
}

__device__ __forceinline__ void mma_tf32(float* c, const uint32_t* a, const uint32_t* b) {
    asm volatile(
        "mma.sync.aligned.m16n8k8.row.col.f32.tf32.tf32.f32 "
        "{%0,%1,%2,%3},{%4,%5,%6,%7},{%8,%9},{%0,%1,%2,%3};\n"
        : "+f"(c[0]), "+f"(c[1]), "+f"(c[2]), "+f"(c[3])
        : "r"(a[0]), "r"(a[1]), "r"(a[2]), "r"(a[3]),
          "r"(b[0]), "r"(b[1]));
}

__device__ __forceinline__ void cpa16(void* smem_dst, const void* gsrc) {
    uint32_t a = (uint32_t)__cvta_generic_to_shared(smem_dst);
    asm volatile("cp.async.cg.shared.global [%0], [%1], 16;" :: "r"(a), "l"(gsrc));
}
__device__ __forceinline__ void cpa_commit() {
    asm volatile("cp.async.commit_group;");
}
template<int N>
__device__ __forceinline__ void cpa_wait() {
    asm volatile("cp.async.wait_group %0;" :: "n"(N));
}

// ============================================================================
// Generic tf32 GEMM, 3-stage cp.async pipeline, ONE __syncthreads per k-iter.
// C[M,N] = A[M,K] @ B[K,N], BM=128, BN=64, BK=16, 256 threads = 8 warps in
// 4(m) x 2(n); each warp 32x32 = 2 m-tiles x 4 n-tiles of m16n8k8.
// MODE 0: QKV projection (A=x, B=Wq|Wkv, scatter epilogue, q *= 0.125)
// MODE 1: QP (A=g_q, B=pemb^T transposed on load, K=64, N=1025 guarded)
// MODE 2: out proj (A=g_ctx, B=Wout, bias add)
// ============================================================================
template<int MODE>
__global__ __launch_bounds__(256) void gemm_tf32(const float* __restrict__ A,
                                                 const float* __restrict__ B,
                                                 const float* __restrict__ B2,
                                                 const float* __restrict__ bias,
                                                 float* __restrict__ Cout) {
    constexpr int K = (MODE == 1) ? 64 : 512;
    constexpr int NIT = K / 16;
    constexpr int BSZ = (MODE == 1) ? 64 * 20 : 16 * 72;

    __shared__ float As[3][128][20];   // [m][k] raw fp32, stride 20 (conflict-free)
    __shared__ float Bs[3][BSZ];       // MODE!=1: [k][n] stride 72; MODE 1: [n][k] stride 20

    const int m0 = blockIdx.y * 128;
    const int n0 = blockIdx.x * 64;
    const int tid = threadIdx.x;
    const int lane = tid & 31;
    const int w = tid >> 5;
    const int wm = w & 3;
    const int wn = w >> 2;
    const int group = lane >> 2;
    const int tid4 = lane & 3;

    const float* Aptr = (MODE == 0) ? A : (MODE == 1 ? g_q : g_ctx);

    float c[2][4][4] = {};

    auto loadA = [&](int buf, int k0) {
        int row = tid >> 1;
        int cg  = (tid & 1) * 8;
        const float* src = &Aptr[(size_t)(m0 + row) * K + k0 + cg];
        cpa16(&As[buf][row][cg],     src);
        cpa16(&As[buf][row][cg + 4], src + 4);
    };
    auto loadB = [&](int buf, int k0) {
        if (MODE == 1) {
            int nl = tid >> 2, kg = (tid & 3) * 4;
            int n = n0 + nl;
            if (n < NP) {
                cpa16(&Bs[buf][nl * 20 + kg], &B[(size_t)n * HD + k0 + kg]);
            } else {
                float* d = &Bs[buf][nl * 20 + kg];
                d[0] = d[1] = d[2] = d[3] = 0.f;
            }
        } else {
            int kk = tid >> 4, cg = (tid & 15) * 4;
            int n = n0 + cg;
            const float* src;
            if (MODE == 0) src = (n < 512) ? &B[(size_t)(k0 + kk) * 512 + n]
                                           : &B2[(size_t)(k0 + kk) * 1024 + (n - 512)];
            else           src = &B[(size_t)(k0 + kk) * 512 + n0 + cg];
            cpa16(&Bs[buf][kk * 72 + cg], src);
        }
    };

    // prologue: tiles 0 and 1 in flight (separate groups)
    loadA(0, 0); loadB(0, 0); cpa_commit();
    if (NIT > 1) { loadA(1, 16); loadB(1, 16); }
    cpa_commit();

    for (int i = 0; i < NIT; i++) {
        const int cur = i % 3;
        cpa_wait<1>();          // tile i complete (only tile i+1's group may remain)
        __syncthreads();        // safe: stage (i+2)%3 was last read at iter i-1
        if (i + 2 < NIT) { loadA((i + 2) % 3, (i + 2) * 16); loadB((i + 2) % 3, (i + 2) * 16); }
        cpa_commit();           // possibly empty group (keeps wait<1> semantics uniform)

        #pragma unroll
        for (int ks = 0; ks < 16; ks += 8) {
            uint32_t a[2][4];
            #pragma unroll
            for (int mt = 0; mt < 2; mt++) {
                int r = wm * 32 + mt * 16;
                a[mt][0] = f2tf32(As[cur][r + group    ][ks + tid4    ]);
                a[mt][1] = f2tf32(As[cur][r + group + 8][ks + tid4    ]);
                a[mt][2] = f2tf32(As[cur][r + group    ][ks + tid4 + 4]);
                a[mt][3] = f2tf32(As[cur][r + group + 8][ks + tid4 + 4]);
            }
            #pragma unroll
            for (int nt = 0; nt < 4; nt++) {
                int cidx = wn * 32 + nt * 8 + group;
                uint32_t b[2];
                if (MODE == 1) {
                    b[0] = f2tf32(Bs[cur][cidx * 20 + ks + tid4    ]);
                    b[1] = f2tf32(Bs[cur][cidx * 20 + ks + tid4 + 4]);
                } else {
                    b[0] = f2tf32(Bs[cur][(ks + tid4    ) * 72 + cidx]);
                    b[1] = f2tf32(Bs[cur][(ks + tid4 + 4) * 72 + cidx]);
                }
                #pragma unroll
                for (int mt = 0; mt < 2; mt++)
                    mma_tf32(c[mt][nt], a[mt], b);
            }
        }
    }

    // ---- epilogue ----
    #pragma unroll
    for (int mt = 0; mt < 2; mt++) {
        #pragma unroll
        for (int nt = 0; nt < 4; nt++) {
            #pragma unroll
            for (int e = 0; e < 4; e++) {
                int row = m0 + wm * 32 + mt * 16 + group + ((e >> 1) * 8);
                int col = n0 + wn * 32 + nt * 8 + 2 * tid4 + (e & 1);
                float val = c[mt][nt][e];
                if (MODE == 0) {
                    int b = row >> 10, s = row & 1023;
                    float* dst; int hcol;
                    if (col < 512)       { dst = g_q; hcol = col;        val *= 0.125f; }
                    else if (col < 1024) { dst = g_k; hcol = col - 512;  }
                    else                 { dst = g_v; hcol = col - 1024; }
                    int h = hcol >> 6, d = hcol & 63;
                    dst[(((size_t)(b * HH + h) << 10) + s) * HD + d] = val;
                } else if (MODE == 1) {
                    if (col < NP) g_qp[(size_t)row * QPS + col] = val;
                } else {
                    Cout[(size_t)row * DD + col] = val + bias[col];
                }
            }
        }
    }
}

// ============================================================================
// Flash attention, warp-local softmax. 128 threads = 4 warps; q-tile 64;
// each warp owns 16 rows x ALL 32 keys and ALL 64 V-columns -> softmax closes
// with intra-quad shuffles only (no cross-warp reduction, no softmax syncs).
// K/V double-buffered cp.async; P is warp-private smem (__syncwarp only).
// ============================================================================
__global__ __launch_bounds__(128) void attn_mma() {
    const int bh = blockIdx.y;
    const int q0 = blockIdx.x * 64;
    const int tid = threadIdx.x;
    const int lane = tid & 31;
    const int w = tid >> 5;          // warp 0..3 -> rows [w*16, w*16+16)
    const int group = lane >> 2;
    const int tid4 = lane & 3;

    __shared__ float sK[2][32][68];   // conflict-free for row-major b-frag reads
    __shared__ float sV[2][32][72];   // stride 72 -> conflict-free column reads
    __shared__ float sP[4][16][36];   // per-warp P slab

    const int row0 = w * 16 + group;
    const int row1 = row0 + 8;
    const size_t qbase = (size_t)bh * SS + q0;
    const size_t qpb0 = (qbase + row0) * QPS + 512;
    const size_t qpb1 = (qbase + row1) * QPS + 512;

    auto loadKV = [&](int buf, int kt) {
        int t0 = kt * 32;
        int row = tid >> 2;              // 0..31
        int cg  = (tid & 3) * 16;        // 0,16,32,48
        size_t base = ((size_t)bh * SS + t0 + row) * HD + cg;
        #pragma unroll
        for (int q = 0; q < 4; q++) {
            cpa16(&sK[buf][row][cg + q * 4], &g_k[base + q * 4]);
            cpa16(&sV[buf][row][cg + q * 4], &g_v[base + q * 4]);
        }
    };

    loadKV(0, 0); cpa_commit();

    // preload Q fragments (overlaps with tile-0 cp.async)
    uint32_t qa[8][4];
    #pragma unroll
    for (int ks = 0; ks < 8; ks++) {
        const float* p0 = &g_q[(qbase + row0) * HD + ks * 8 + tid4];
        const float* p1 = &g_q[(qbase + row1) * HD + ks * 8 + tid4];
        qa[ks][0] = f2tf32(p0[0]);
        qa[ks][1] = f2tf32(p1[0]);
        qa[ks][2] = f2tf32(p0[4]);
        qa[ks][3] = f2tf32(p1[4]);
    }

    float cO[8][4] = {};
    float rmax0 = -1e30f, rmax1 = -1e30f;
    float rsum0 = 0.f, rsum1 = 0.f;

    for (int kt = 0; kt < SS / 32; kt++) {
        const int cur = kt & 1;
        const int t0 = kt * 32;
        if (kt + 1 < SS / 32) {
            loadKV(cur ^ 1, kt + 1);
            cpa_commit();
            cpa_wait<1>();
        } else {
            cpa_wait<0>();
        }
        __syncthreads();

        // ---- S = Q @ K^T : 16 rows x 32 keys per warp (4 n-tiles) ----
        float cS[4][4] = {};
        #pragma unroll
        for (int ks = 0; ks < 8; ks++) {
            #pragma unroll
            for (int nt = 0; nt < 4; nt++) {
                int kc = nt * 8 + group;
                uint32_t b[2];
                b[0] = f2tf32(sK[cur][kc][ks * 8 + tid4    ]);
                b[1] = f2tf32(sK[cur][kc][ks * 8 + tid4 + 4]);
                mma_tf32(cS[nt], qa[ks], b);
            }
        }

        // ---- positional bias + warp-local row max ----
        float mloc0 = -1e30f, mloc1 = -1e30f;
        const int s0 = q0 + row0, s1 = q0 + row1;
        #pragma unroll
        for (int nt = 0; nt < 4; nt++) {
            #pragma unroll
            for (int e = 0; e < 4; e++) {
                int t = t0 + nt * 8 + 2 * tid4 + (e & 1);
                int s_g = (e < 2) ? s0 : s1;
                int dlt = s_g - t;
                dlt = min(512, max(-512, dlt));
                float v = cS[nt][e] + g_qp[((e < 2) ? qpb0 : qpb1) + dlt];
                cS[nt][e] = v;
                if (e < 2) mloc0 = fmaxf(mloc0, v);
                else       mloc1 = fmaxf(mloc1, v);
            }
        }
        // full row = 4 lanes of the quad
        mloc0 = fmaxf(mloc0, __shfl_xor_sync(0xffffffffu, mloc0, 1));
        mloc0 = fmaxf(mloc0, __shfl_xor_sync(0xffffffffu, mloc0, 2));
        mloc1 = fmaxf(mloc1, __shfl_xor_sync(0xffffffffu, mloc1, 1));
        mloc1 = fmaxf(mloc1, __shfl_xor_sync(0xffffffffu, mloc1, 2));

        float mnew0 = fmaxf(rmax0, mloc0);
        float mnew1 = fmaxf(rmax1, mloc1);
        float corr0 = __expf(rmax0 - mnew0);
        float corr1 = __expf(rmax1 - mnew1);
        rmax0 = mnew0; rmax1 = mnew1;

        float ls0 = 0.f, ls1 = 0.f;
        #pragma unroll
        for (int nt = 0; nt < 4; nt++) {
            #pragma unroll
            for (int e = 0; e < 4; e++) {
                float p = __expf(cS[nt][e] - ((e < 2) ? mnew0 : mnew1));
                if (e < 2) ls0 += p; else ls1 += p;
                int rl = (e < 2) ? group : group + 8;
                sP[w][rl][nt * 8 + 2 * tid4 + (e & 1)] = p;
            }
        }
        ls0 += __shfl_xor_sync(0xffffffffu, ls0, 1);
        ls0 += __shfl_xor_sync(0xffffffffu, ls0, 2);
        ls1 += __shfl_xor_sync(0xffffffffu, ls1, 1);
        ls1 += __shfl_xor_sync(0xffffffffu, ls1, 2);
        rsum0 = rsum0 * corr0 + ls0;
        rsum1 = rsum1 * corr1 + ls1;

        #pragma unroll
        for (int nt2 = 0; nt2 < 8; nt2++) {
            cO[nt2][0] *= corr0; cO[nt2][1] *= corr0;
            cO[nt2][2] *= corr1; cO[nt2][3] *= corr1;
        }
        __syncwarp();

        // ---- O += P @ V : 16 rows x 64 hd-cols per warp (8 n-tiles) ----
        #pragma unroll
        for (int ks = 0; ks < 4; ks++) {
            uint32_t a[4];
            a[0] = f2tf32(sP[w][group    ][ks * 8 + tid4    ]);
            a[1] = f2tf32(sP[w][group + 8][ks * 8 + tid4    ]);
            a[2] = f2tf32(sP[w][group    ][ks * 8 + tid4 + 4]);
            a[3] = f2tf32(sP[w][group + 8][ks * 8 + tid4 + 4]);
            #pragma unroll
            for (int nt2 = 0; nt2 < 8; nt2++) {
                int dc = nt2 * 8 + group;
                uint32_t b[2];
                b[0] = f2tf32(sV[cur][ks * 8 + tid4    ][dc]);
                b[1] = f2tf32(sV[cur][ks * 8 + tid4 + 4][dc]);
                mma_tf32(cO[nt2], a, b);
            }
        }
        __syncwarp();   // P slab reuse next iter (warp-private)
        __syncthreads();  // protect cur K/V buffer before next cp.async overwrite
    }

    // ---- write ctx [b, s, h*64+d] ----
    const int b = bh >> 3, h = bh & 7;
    const float inv0 = 1.0f / rsum0, inv1 = 1.0f / rsum1;
    #pragma unroll
    for (int nt2 = 0; nt2 < 8; nt2++) {
        #pragma unroll
        for (int e = 0; e < 4; e++) {
            int d = nt2 * 8 + 2 * tid4 + (e & 1);
            int s = q0 + ((e < 2) ? row0 : row1);
            float val = cO[nt2][e] * ((e < 2) ? inv0 : inv1);
            g_ctx[((size_t)(b * SS + s)) * (HH * HD) + h * HD + d] = val;
        }
    }
}

// ============================================================================
extern "C" void kernel_launch(void* const* d_in, const int* in_sizes, int n_in,
                              void* d_out, int out_size) {
    const float* x    = (const float*)d_in[0];
    // d_in[1] = attn_mask (unused by reference)
    const float* Wq   = (const float*)d_in[2];
    const float* Wkv  = (const float*)d_in[3];
    const float* Wout = (const float*)d_in[4];
    const float* bout = (const float*)d_in[5];
    const float* pemb = (const float*)d_in[6];
    float* out = (float*)d_out;

    // 1) QKV projection: M=4096, N=1536, K=512
    gemm_tf32<0><<<dim3(1536 / 64, 4096 / 128), 256>>>(x, Wq, Wkv, nullptr, nullptr);

    // 2) qp = q @ pemb^T: M=32768, N=1025, K=64
    gemm_tf32<1><<<dim3((NP + 63) / 64, (BB * HH * SS) / 128), 256>>>(nullptr, pemb, nullptr, nullptr, nullptr);

    // 3) attention: 16 q-tiles x 32 (b,h)
    attn_mma<<<dim3(SS / 64, BB * HH), 128>>>();

    // 4) out projection: M=4096, N=512, K=512
    gemm_tf32<2><<<dim3(DD / 64, 4096 / 128), 256>>>(nullptr, Wout, nullptr, bout, out);
}

// round 10
// speedup vs baseline: 1.6825x; 1.3590x over previous
#include <cuda_runtime.h>
#include <cuda_fp16.h>
#include <math.h>
#include <stdint.h>

#define BB 4
#define SS 1024
#define DD 512
#define HH 8
#define HD 64
#define NP 1025    // pemb rows (2*512+1)
#define QPS 1032   // padded qp row stride

// ---------------- scratch (device globals; allocation-free) ----------------
__device__ float  g_q [BB*HH*SS*HD];             // fp32 [b,h,s,d], q*0.125 (qp GEMM input)
__device__ __half g_qh[BB*HH*SS*HD];             // fp16 copy for attention
__device__ __half g_kh[BB*HH*SS*HD];             // fp16 [b,h,s,d]
__device__ __half g_vt[BB*HH*HD*SS];             // fp16 [b,h,d,s] (transposed V)
__device__ __half g_qph[(size_t)BB*HH*SS*QPS];   // fp16 [b,h,s, 1032(1025 used)]
__device__ float  g_ctx[BB*SS*HH*HD];            // fp32 [b,s, h*64+d]

// ---------------- helpers ----------------
__device__ __forceinline__ uint32_t f2tf32(float f) {
    uint32_t u;
    asm("cvt.rna.tf32.f32 %0, %1;" : "=r"(u) : "f"(f));
    return u;
}

__device__ __forceinline__ void mma_tf32(float* c, const uint32_t* a, const uint32_t* b) {
    asm volatile(
        "mma.sync.aligned.m16n8k8.row.col.f32.tf32.tf32.f32 "
        "{%0,%1,%2,%3},{%4,%5,%6,%7},{%8,%9},{%0,%1,%2,%3};\n"
        : "+f"(c[0]), "+f"(c[1]), "+f"(c[2]), "+f"(c[3])
        : "r"(a[0]), "r"(a[1]), "r"(a[2]), "r"(a[3]),
          "r"(b[0]), "r"(b[1]));
}

__device__ __forceinline__ void mma_f16(float* c, const uint32_t* a, const uint32_t* b) {
    asm volatile(
        "mma.sync.aligned.m16n8k16.row.col.f32.f16.f16.f32 "
        "{%0,%1,%2,%3},{%4,%5,%6,%7},{%8,%9},{%0,%1,%2,%3};\n"
        : "+f"(c[0]), "+f"(c[1]), "+f"(c[2]), "+f"(c[3])
        : "r"(a[0]), "r"(a[1]), "r"(a[2]), "r"(a[3]),
          "r"(b[0]), "r"(b[1]));
}

__device__ __forceinline__ void cpa16(void* smem_dst, const void* gsrc) {
    uint32_t a = (uint32_t)__cvta_generic_to_shared(smem_dst);
    asm volatile("cp.async.cg.shared.global [%0], [%1], 16;" :: "r"(a), "l"(gsrc));
}
__device__ __forceinline__ void cpa_commit() {
    asm volatile("cp.async.commit_group;");
}
template<int N>
__device__ __forceinline__ void cpa_wait() {
    asm volatile("cp.async.wait_group %0;" :: "n"(N));
}

// ============================================================================
// Generic tf32 GEMM, 3-stage cp.async pipeline, one __syncthreads per k-iter.
// BM=128, BN=64, BK=16, 256 threads = 8 warps (4m x 2n), warp 32x32.
// MODE 0: QKV proj (epilogue: g_q fp32 + g_qh/g_kh fp16, g_vt fp16 transposed)
// MODE 1: QP (K=64, B=pemb^T on load; epilogue: fp16 g_qph, N=1025 guarded)
// MODE 2: out proj (bias add, fp32 out)
// ============================================================================
template<int MODE>
__global__ __launch_bounds__(256) void gemm_tf32(const float* __restrict__ A,
                                                 const float* __restrict__ B,
                                                 const float* __restrict__ B2,
                                                 const float* __restrict__ bias,
                                                 float* __restrict__ Cout) {
    constexpr int K = (MODE == 1) ? 64 : 512;
    constexpr int NIT = K / 16;
    constexpr int BSZ = (MODE == 1) ? 64 * 20 : 16 * 72;

    __shared__ float As[3][128][20];
    __shared__ float Bs[3][BSZ];

    const int m0 = blockIdx.y * 128;
    const int n0 = blockIdx.x * 64;
    const int tid = threadIdx.x;
    const int lane = tid & 31;
    const int w = tid >> 5;
    const int wm = w & 3;
    const int wn = w >> 2;
    const int group = lane >> 2;
    const int tid4 = lane & 3;

    const float* Aptr = (MODE == 0) ? A : (MODE == 1 ? g_q : g_ctx);

    float c[2][4][4] = {};

    auto loadA = [&](int buf, int k0) {
        int row = tid >> 1;
        int cg  = (tid & 1) * 8;
        const float* src = &Aptr[(size_t)(m0 + row) * K + k0 + cg];
        cpa16(&As[buf][row][cg],     src);
        cpa16(&As[buf][row][cg + 4], src + 4);
    };
    auto loadB = [&](int buf, int k0) {
        if (MODE == 1) {
            int nl = tid >> 2, kg = (tid & 3) * 4;
            int n = n0 + nl;
            if (n < NP) {
                cpa16(&Bs[buf][nl * 20 + kg], &B[(size_t)n * HD + k0 + kg]);
            } else {
                float* d = &Bs[buf][nl * 20 + kg];
                d[0] = d[1] = d[2] = d[3] = 0.f;
            }
        } else {
            int kk = tid >> 4, cg = (tid & 15) * 4;
            int n = n0 + cg;
            const float* src;
            if (MODE == 0) src = (n < 512) ? &B[(size_t)(k0 + kk) * 512 + n]
                                           : &B2[(size_t)(k0 + kk) * 1024 + (n - 512)];
            else           src = &B[(size_t)(k0 + kk) * 512 + n0 + cg];
            cpa16(&Bs[buf][kk * 72 + cg], src);
        }
    };

    loadA(0, 0); loadB(0, 0); cpa_commit();
    if (NIT > 1) { loadA(1, 16); loadB(1, 16); }
    cpa_commit();

    for (int i = 0; i < NIT; i++) {
        const int cur = i % 3;
        cpa_wait<1>();
        __syncthreads();
        if (i + 2 < NIT) { loadA((i + 2) % 3, (i + 2) * 16); loadB((i + 2) % 3, (i + 2) * 16); }
        cpa_commit();

        #pragma unroll
        for (int ks = 0; ks < 16; ks += 8) {
            uint32_t a[2][4];
            #pragma unroll
            for (int mt = 0; mt < 2; mt++) {
                int r = wm * 32 + mt * 16;
                a[mt][0] = f2tf32(As[cur][r + group    ][ks + tid4    ]);
                a[mt][1] = f2tf32(As[cur][r + group + 8][ks + tid4    ]);
                a[mt][2] = f2tf32(As[cur][r + group    ][ks + tid4 + 4]);
                a[mt][3] = f2tf32(As[cur][r + group + 8][ks + tid4 + 4]);
            }
            #pragma unroll
            for (int nt = 0; nt < 4; nt++) {
                int cidx = wn * 32 + nt * 8 + group;
                uint32_t b[2];
                if (MODE == 1) {
                    b[0] = f2tf32(Bs[cur][cidx * 20 + ks + tid4    ]);
                    b[1] = f2tf32(Bs[cur][cidx * 20 + ks + tid4 + 4]);
                } else {
                    b[0] = f2tf32(Bs[cur][(ks + tid4    ) * 72 + cidx]);
                    b[1] = f2tf32(Bs[cur][(ks + tid4 + 4) * 72 + cidx]);
                }
                #pragma unroll
                for (int mt = 0; mt < 2; mt++)
                    mma_tf32(c[mt][nt], a[mt], b);
            }
        }
    }

    // ---- epilogue (pairs: e0/e1 = row r0 cols col,col+1; e2/e3 = row r0+8) ----
    #pragma unroll
    for (int mt = 0; mt < 2; mt++) {
        #pragma unroll
        for (int nt = 0; nt < 4; nt++) {
            #pragma unroll
            for (int half_ : {0, 1}) {
                int row = m0 + wm * 32 + mt * 16 + group + half_ * 8;
                int col = n0 + wn * 32 + nt * 8 + 2 * tid4;
                float v0 = c[mt][nt][half_ * 2 + 0];
                float v1 = c[mt][nt][half_ * 2 + 1];
                if (MODE == 0) {
                    int b = row >> 10, s = row & 1023;
                    int hcol = (col < 512) ? col : (col < 1024 ? col - 512 : col - 1024);
                    int h = hcol >> 6, d = hcol & 63;
                    size_t base = (((size_t)(b * HH + h) << 10) + s) * HD + d;
                    if (col < 512) {
                        v0 *= 0.125f; v1 *= 0.125f;
                        *(float2*)&g_q[base] = make_float2(v0, v1);
                        *(__half2*)&g_qh[base] = __floats2half2_rn(v0, v1);
                    } else if (col < 1024) {
                        *(__half2*)&g_kh[base] = __floats2half2_rn(v0, v1);
                    } else {
                        size_t tb = ((size_t)(b * HH + h) * HD + d) * SS + s;
                        g_vt[tb]      = __float2half_rn(v0);
                        g_vt[tb + SS] = __float2half_rn(v1);
                    }
                } else if (MODE == 1) {
                    size_t base = (size_t)row * QPS + col;
                    if (col + 1 < NP)
                        *(__half2*)&g_qph[base] = __floats2half2_rn(v0, v1);
                    else if (col < NP)
                        g_qph[base] = __float2half_rn(v0);
                } else {
                    Cout[(size_t)row * DD + col]     = v0 + bias[col];
                    Cout[(size_t)row * DD + col + 1] = v1 + bias[col + 1];
                }
            }
        }
    }
}

// ============================================================================
// Flash attention, fp16 m16n8k16, warp-local softmax. 128 threads = 4 warps;
// q-tile 64, k-tile 32; each warp owns 16 rows x all keys x all 64 V-cols.
// K/V double-buffered cp.async; V pre-transposed in gmem; bias prefetched.
// ============================================================================
__global__ __launch_bounds__(128) void attn_mma() {
    const int bh = blockIdx.y;
    const int q0 = blockIdx.x * 64;
    const int tid = threadIdx.x;
    const int lane = tid & 31;
    const int w = tid >> 5;
    const int group = lane >> 2;
    const int tid4 = lane & 3;

    __shared__ __half sK [2][32][72];   // [key][d]  stride 72 -> conflict-free b-frags
    __shared__ __half sVT[2][64][40];   // [d][key]  stride 40 -> conflict-free b-frags
    __shared__ __half sP [4][16][40];   // per-warp P slab

    const int row0 = w * 16 + group;
    const int row1 = row0 + 8;
    const size_t qbase = (size_t)bh * SS + q0;
    const size_t qpb0 = (qbase + row0) * QPS + 512;
    const size_t qpb1 = (qbase + row1) * QPS + 512;

    auto loadKV = [&](int buf, int kt) {
        int t0 = kt * 32;
        {   // K: 32 rows x 64 halves (128B/row)
            int row = tid >> 2, seg = (tid & 3) * 16;
            const __half* src = &g_kh[((size_t)bh * SS + t0 + row) * HD + seg];
            cpa16(&sK[buf][row][seg],     src);
            cpa16(&sK[buf][row][seg + 8], src + 8);
        }
        {   // VT: 64 rows x 32 halves (64B/row)
            int row = tid >> 1, seg = (tid & 1) * 16;
            const __half* src = &g_vt[((size_t)bh * HD + row) * SS + t0 + seg];
            cpa16(&sVT[buf][row][seg],     src);
            cpa16(&sVT[buf][row][seg + 8], src + 8);
        }
    };

    loadKV(0, 0); cpa_commit();

    // preload Q fragments (half2 direct from gmem; overlaps tile-0 cp.async)
    uint32_t qa[4][4];
    #pragma unroll
    for (int ks = 0; ks < 4; ks++) {
        const __half* p0 = &g_qh[(qbase + row0) * HD + ks * 16 + 2 * tid4];
        const __half* p1 = &g_qh[(qbase + row1) * HD + ks * 16 + 2 * tid4];
        qa[ks][0] = *(const uint32_t*)p0;
        qa[ks][1] = *(const uint32_t*)p1;
        qa[ks][2] = *(const uint32_t*)(p0 + 8);
        qa[ks][3] = *(const uint32_t*)(p1 + 8);
    }

    float cO[8][4] = {};
    float rmax0 = -1e30f, rmax1 = -1e30f;
    float rsum0 = 0.f, rsum1 = 0.f;
    const int s0 = q0 + row0, s1 = q0 + row1;

    for (int kt = 0; kt < SS / 32; kt++) {
        const int cur = kt & 1;
        const int t0 = kt * 32;
        if (kt + 1 < SS / 32) {
            loadKV(cur ^ 1, kt + 1);
            cpa_commit();
            cpa_wait<1>();
        } else {
            cpa_wait<0>();
        }
        __syncthreads();

        // ---- bias prefetch: 16 scattered half LDGs, issued before S-mma ----
        __half hb[4][4];
        #pragma unroll
        for (int nt = 0; nt < 4; nt++) {
            #pragma unroll
            for (int e = 0; e < 4; e++) {
                int t = t0 + nt * 8 + 2 * tid4 + (e & 1);
                int s_g = (e < 2) ? s0 : s1;
                int dlt = s_g - t;
                dlt = min(512, max(-512, dlt));
                hb[nt][e] = g_qph[((e < 2) ? qpb0 : qpb1) + dlt];
            }
        }

        // ---- S = Q @ K^T : 16 rows x 32 keys per warp, fp16 k16 ----
        float cS[4][4] = {};
        #pragma unroll
        for (int ks = 0; ks < 4; ks++) {
            #pragma unroll
            for (int nt = 0; nt < 4; nt++) {
                int kc = nt * 8 + group;
                uint32_t b[2];
                b[0] = *(const uint32_t*)&sK[cur][kc][ks * 16 + 2 * tid4];
                b[1] = *(const uint32_t*)&sK[cur][kc][ks * 16 + 2 * tid4 + 8];
                mma_f16(cS[nt], qa[ks], b);
            }
        }

        // ---- bias add + warp-local row max ----
        float mloc0 = -1e30f, mloc1 = -1e30f;
        #pragma unroll
        for (int nt = 0; nt < 4; nt++) {
            #pragma unroll
            for (int e = 0; e < 4; e++) {
                float v = cS[nt][e] + __half2float(hb[nt][e]);
                cS[nt][e] = v;
                if (e < 2) mloc0 = fmaxf(mloc0, v);
                else       mloc1 = fmaxf(mloc1, v);
            }
        }
        mloc0 = fmaxf(mloc0, __shfl_xor_sync(0xffffffffu, mloc0, 1));
        mloc0 = fmaxf(mloc0, __shfl_xor_sync(0xffffffffu, mloc0, 2));
        mloc1 = fmaxf(mloc1, __shfl_xor_sync(0xffffffffu, mloc1, 1));
        mloc1 = fmaxf(mloc1, __shfl_xor_sync(0xffffffffu, mloc1, 2));

        float mnew0 = fmaxf(rmax0, mloc0);
        float mnew1 = fmaxf(rmax1, mloc1);
        float corr0 = __expf(rmax0 - mnew0);
        float corr1 = __expf(rmax1 - mnew1);
        rmax0 = mnew0; rmax1 = mnew1;

        float ls0 = 0.f, ls1 = 0.f;
        #pragma unroll
        for (int nt = 0; nt < 4; nt++) {
            float p0 = __expf(cS[nt][0] - mnew0);
            float p1 = __expf(cS[nt][1] - mnew0);
            float p2 = __expf(cS[nt][2] - mnew1);
            float p3 = __expf(cS[nt][3] - mnew1);
            ls0 += p0 + p1; ls1 += p2 + p3;
            *(__half2*)&sP[w][group    ][nt * 8 + 2 * tid4] = __floats2half2_rn(p0, p1);
            *(__half2*)&sP[w][group + 8][nt * 8 + 2 * tid4] = __floats2half2_rn(p2, p3);
        }
        ls0 += __shfl_xor_sync(0xffffffffu, ls0, 1);
        ls0 += __shfl_xor_sync(0xffffffffu, ls0, 2);
        ls1 += __shfl_xor_sync(0xffffffffu, ls1, 1);
        ls1 += __shfl_xor_sync(0xffffffffu, ls1, 2);
        rsum0 = rsum0 * corr0 + ls0;
        rsum1 = rsum1 * corr1 + ls1;

        #pragma unroll
        for (int nt2 = 0; nt2 < 8; nt2++) {
            cO[nt2][0] *= corr0; cO[nt2][1] *= corr0;
            cO[nt2][2] *= corr1; cO[nt2][3] *= corr1;
        }
        __syncwarp();

        // ---- O += P @ V : 16 rows x 64 cols per warp, fp16 k16 x2 ----
        #pragma unroll
        for (int ks2 = 0; ks2 < 2; ks2++) {
            uint32_t a[4];
            a[0] = *(const uint32_t*)&sP[w][group    ][ks2 * 16 + 2 * tid4];
            a[1] = *(const uint32_t*)&sP[w][group + 8][ks2 * 16 + 2 * tid4];
            a[2] = *(const uint32_t*)&sP[w][group    ][ks2 * 16 + 2 * tid4 + 8];
            a[3] = *(const uint32_t*)&sP[w][group + 8][ks2 * 16 + 2 * tid4 + 8];
            #pragma unroll
            for (int nt2 = 0; nt2 < 8; nt2++) {
                int dc = nt2 * 8 + group;
                uint32_t b[2];
                b[0] = *(const uint32_t*)&sVT[cur][dc][ks2 * 16 + 2 * tid4];
                b[1] = *(const uint32_t*)&sVT[cur][dc][ks2 * 16 + 2 * tid4 + 8];
                mma_f16(cO[nt2], a, b);
            }
        }
        __syncwarp();
        __syncthreads();   // protect cur K/V buffer before next overwrite
    }

    // ---- write ctx [b, s, h*64+d] ----
    const int b = bh >> 3, h = bh & 7;
    const float inv0 = 1.0f / rsum0, inv1 = 1.0f / rsum1;
    #pragma unroll
    for (int nt2 = 0; nt2 < 8; nt2++) {
        #pragma unroll
        for (int e = 0; e < 4; e++) {
            int d = nt2 * 8 + 2 * tid4 + (e & 1);
            int s = q0 + ((e < 2) ? row0 : row1);
            float val = cO[nt2][e] * ((e < 2) ? inv0 : inv1);
            g_ctx[((size_t)(b * SS + s)) * (HH * HD) + h * HD + d] = val;
        }
    }
}

// ============================================================================
extern "C" void kernel_launch(void* const* d_in, const int* in_sizes, int n_in,
                              void* d_out, int out_size) {
    const float* x    = (const float*)d_in[0];
    // d_in[1] = attn_mask (unused by reference)
    const float* Wq   = (const float*)d_in[2];
    const float* Wkv  = (const float*)d_in[3];
    const float* Wout = (const float*)d_in[4];
    const float* bout = (const float*)d_in[5];
    const float* pemb = (const float*)d_in[6];
    float* out = (float*)d_out;

    // 1) QKV projection: M=4096, N=1536, K=512
    gemm_tf32<0><<<dim3(1536 / 64, 4096 / 128), 256>>>(x, Wq, Wkv, nullptr, nullptr);

    // 2) qp = q @ pemb^T: M=32768, N=1025, K=64 (fp16 output)
    gemm_tf32<1><<<dim3((NP + 63) / 64, (BB * HH * SS) / 128), 256>>>(nullptr, pemb, nullptr, nullptr, nullptr);

    // 3) attention: 16 q-tiles x 32 (b,h)
    attn_mma<<<dim3(SS / 64, BB * HH), 128>>>();

    // 4) out projection: M=4096, N=512, K=512
    gemm_tf32<2><<<dim3(DD / 64, 4096 / 128), 256>>>(nullptr, Wout, nullptr, bout, out);
}